// round 9
// baseline (speedup 1.0000x reference)
#include <cuda_runtime.h>

#define DIMC 192
#define HEADS 6
#define HD 32
#define SSH 4
#define NTOK 64
#define NWIN 4096
#define SCALE 0.17677669529663687f   // 32^-0.5
#define QS 580                        // qkv_s row stride in floats (64 rows x 580)

typedef unsigned long long u64;

// ---------------- scratch (device globals; no allocations allowed) ----------
__device__ float g_wT[DIMC * 576];    // qkv_w transposed: [k][o]
__device__ float g_pT[DIMC * DIMC];   // proj_w transposed: [k][o]

// ---------------- f32x2 helpers ----------------------------------------------
__device__ __forceinline__ u64 splat2(float v) {
    u64 r; asm("mov.b64 %0,{%1,%1};" : "=l"(r) : "f"(v)); return r;
}
__device__ __forceinline__ void ffma2(u64& d, u64 a, u64 b) {
    asm("fma.rn.f32x2 %0,%1,%2,%0;" : "+l"(d) : "l"(a), "l"(b));
}
__device__ __forceinline__ float2 unpack2(u64 v) {
    float2 r; asm("mov.b64 {%0,%1},%2;" : "=f"(r.x), "=f"(r.y) : "l"(v)); return r;
}

// ---------------- kernel 0: weight transpose ---------------------------------
__global__ void transpose_weights(const float* __restrict__ qkv_w,
                                  const float* __restrict__ proj_w) {
    int idx = blockIdx.x * 256 + threadIdx.x;
    if (idx < 576 * DIMC) {
        int o = idx / DIMC, k = idx % DIMC;
        g_wT[k * 576 + o] = qkv_w[idx];
    }
    if (idx < DIMC * DIMC) {
        int o = idx / DIMC, k = idx % DIMC;
        g_pT[k * DIMC + o] = proj_w[idx];
    }
}

// ---------------- fused per-window megakernel --------------------------------
// smem layout (floats):
//   qkv_s [64][QS]        : QKV activations, token-major  (37120)
//   Xs    [192][64]       : gathered input, channel-major; reused as Os (12288)
//   rpbs  [1350]          : relative position bias table
//   regsh [64] (int)      : shift-mask region id per token
__global__ __launch_bounds__(256, 1) void swin_kernel(
    const float* __restrict__ x, const float* __restrict__ qkv_b,
    const float* __restrict__ proj_b, const float* __restrict__ rpb_table,
    float* __restrict__ out)
{
    extern __shared__ float sm[];
    float* qkv_s = sm;
    float* Xs    = sm + NTOK * QS;
    float* rpbs  = Xs + DIMC * NTOK;
    int*   regsh = (int*)(rpbs + 1350);

    int win = blockIdx.x;
    int b = win >> 10, wy = (win >> 5) & 31, wx = win & 31;
    int tid  = threadIdx.x;
    int lane = tid & 31, warp = tid >> 5;

    // ---- phase 0: gather shifted window + rpb + region ids ----
    int y0 = wy * 8 + SSH, x0 = wx * 8 + SSH;
    for (int idx = tid; idx < DIMC * NTOK; idx += 256) {
        int t = idx & 63, c = idx >> 6;
        int yy = (y0 + (t >> 3)) & 255;
        int xx = (x0 + (t & 7)) & 255;
        Xs[idx] = x[(size_t)(b * DIMC + c) * 65536 + yy * 256 + xx];
    }
    for (int idx = tid; idx < 1350; idx += 256) rpbs[idx] = rpb_table[idx];
    if (tid < 64) {
        int iy = tid >> 3, ix = tid & 7;
        int yt = wy * 8 + iy, xt = wx * 8 + ix;
        int ry = (yt < 248) ? 0 : ((yt < 252) ? 1 : 2);
        int rx = (xt < 248) ? 0 : ((xt < 252) ? 1 : 2);
        regsh[tid] = ry * 3 + rx;
    }
    __syncthreads();

    int t0 = warp * 8;   // 8 tokens per warp (one window row), shared by all lanes

    // ---- phase 1: QKV GEMM  (out[t][o] = sum_k Xs[k][t] * wT[k][o] + b[o]) ----
    {
        const float* __restrict__ wT = g_wT;
        #pragma unroll 1
        for (int pass = 0; pass < 2; pass++) {
            int ob = pass * 256 + lane * 8;
            u64 acc[4][8];                      // [output-pair][token]
            {
                const u64* bp = (const u64*)&qkv_b[ob];
                #pragma unroll
                for (int op = 0; op < 4; op++) {
                    u64 bv = bp[op];
                    #pragma unroll
                    for (int t = 0; t < 8; t++) acc[op][t] = bv;
                }
            }
            #pragma unroll 4
            for (int k = 0; k < DIMC; k++) {
                float4 a01 = *(const float4*)&Xs[k * 64 + t0];      // broadcast LDS
                float4 a23 = *(const float4*)&Xs[k * 64 + t0 + 4];
                const u64* wr = (const u64*)&wT[k * 576 + ob];      // coalesced LDG
                u64 w0 = wr[0], w1 = wr[1], w2 = wr[2], w3 = wr[3];
                u64 as[8];
                as[0] = splat2(a01.x); as[1] = splat2(a01.y);
                as[2] = splat2(a01.z); as[3] = splat2(a01.w);
                as[4] = splat2(a23.x); as[5] = splat2(a23.y);
                as[6] = splat2(a23.z); as[7] = splat2(a23.w);
                #pragma unroll
                for (int t = 0; t < 8; t++) {
                    ffma2(acc[0][t], w0, as[t]);
                    ffma2(acc[1][t], w1, as[t]);
                    ffma2(acc[2][t], w2, as[t]);
                    ffma2(acc[3][t], w3, as[t]);
                }
            }
            #pragma unroll
            for (int t = 0; t < 8; t++) {
                ulonglong2* dst = (ulonglong2*)&qkv_s[(t0 + t) * QS + ob];
                dst[0] = make_ulonglong2(acc[0][t], acc[1][t]);
                dst[1] = make_ulonglong2(acc[2][t], acc[3][t]);
            }
        }
        // tail pass: outputs 512..575 (2 per lane)
        {
            int ob = 512 + lane * 2;
            u64 acc[8];
            u64 bv = *(const u64*)&qkv_b[ob];
            #pragma unroll
            for (int t = 0; t < 8; t++) acc[t] = bv;
            #pragma unroll 4
            for (int k = 0; k < DIMC; k++) {
                float4 a01 = *(const float4*)&Xs[k * 64 + t0];
                float4 a23 = *(const float4*)&Xs[k * 64 + t0 + 4];
                u64 w = *(const u64*)&wT[k * 576 + ob];
                ffma2(acc[0], w, splat2(a01.x));
                ffma2(acc[1], w, splat2(a01.y));
                ffma2(acc[2], w, splat2(a01.z));
                ffma2(acc[3], w, splat2(a01.w));
                ffma2(acc[4], w, splat2(a23.x));
                ffma2(acc[5], w, splat2(a23.y));
                ffma2(acc[6], w, splat2(a23.z));
                ffma2(acc[7], w, splat2(a23.w));
            }
            #pragma unroll
            for (int t = 0; t < 8; t++)
                *(u64*)&qkv_s[(t0 + t) * QS + ob] = acc[t];
        }
    }
    __syncthreads();

    // ---- phase 2: attention (6 heads x 64 query rows = 384 items) ----
    for (int it = tid; it < HEADS * NTOK; it += 256) {
        int h = it >> 6, i = it & 63;
        int iy = i >> 3, ix = i & 7;
        int regi = regsh[i];
        u64 q2[16];
        {
            const ulonglong2* qp = (const ulonglong2*)&qkv_s[i * QS + h * HD];
            #pragma unroll
            for (int m = 0; m < 8; m++) {
                ulonglong2 v = qp[m];
                q2[2 * m] = v.x; q2[2 * m + 1] = v.y;
            }
        }
        u64 acc2[16];
        #pragma unroll
        for (int dp = 0; dp < 16; dp++) acc2[dp] = 0ull;
        float l = 0.f;
        const float* kbase = &qkv_s[DIMC + h * HD];
        const float* vbase = &qkv_s[2 * DIMC + h * HD];
        int rb = (iy + 7) * 15 + (ix + 7);
        #pragma unroll 2
        for (int j = 0; j < NTOK; j++) {
            const ulonglong2* kp = (const ulonglong2*)(kbase + j * QS);
            u64 s2 = 0ull;
            #pragma unroll
            for (int m = 0; m < 8; m++) {
                ulonglong2 kv = kp[m];
                ffma2(s2, q2[2 * m], kv.x);
                ffma2(s2, q2[2 * m + 1], kv.y);
            }
            float2 sp = unpack2(s2);
            float s = sp.x + sp.y;
            float bias = rpbs[(rb - (j >> 3) * 15 - (j & 7)) * HEADS + h];
            float msk  = (regi != regsh[j]) ? -100.f : 0.f;
            float e = __expf(fmaf(s, SCALE, bias + msk));
            l += e;
            u64 es = splat2(e);
            const ulonglong2* vp = (const ulonglong2*)(vbase + j * QS);
            #pragma unroll
            for (int m = 0; m < 8; m++) {
                ulonglong2 vv = vp[m];
                ffma2(acc2[2 * m], es, vv.x);
                ffma2(acc2[2 * m + 1], es, vv.y);
            }
        }
        float invl = 1.f / l;
        float* Ob = Xs + (h * HD) * 64 + i;   // Os[c][t], reuses Xs region
        #pragma unroll
        for (int dp = 0; dp < 16; dp++) {
            float2 v = unpack2(acc2[dp]);
            Ob[(2 * dp) * 64]     = v.x * invl;
            Ob[(2 * dp + 1) * 64] = v.y * invl;
        }
    }
    __syncthreads();

    // ---- phase 3: proj GEMM + reverse-shift scatter (192 outs: lanes 0..23) ----
    if (lane < 24) {
        int ob = lane * 8;
        u64 acc[8][4];                         // [output][token-pair]
        #pragma unroll
        for (int oo = 0; oo < 8; oo++) {
            u64 bv = splat2(proj_b[ob + oo]);
            #pragma unroll
            for (int tp = 0; tp < 4; tp++) acc[oo][tp] = bv;
        }
        const float* __restrict__ pT = g_pT;
        #pragma unroll 4
        for (int k = 0; k < DIMC; k++) {
            const ulonglong2* ar = (const ulonglong2*)&Xs[k * 64 + t0];   // Os broadcast
            ulonglong2 a01 = ar[0], a23 = ar[1];
            const float4* wr = (const float4*)&pT[k * DIMC + ob];
            float4 w0 = wr[0], w1 = wr[1];
            u64 ws;
            ws = splat2(w0.x);
            ffma2(acc[0][0], ws, a01.x); ffma2(acc[0][1], ws, a01.y);
            ffma2(acc[0][2], ws, a23.x); ffma2(acc[0][3], ws, a23.y);
            ws = splat2(w0.y);
            ffma2(acc[1][0], ws, a01.x); ffma2(acc[1][1], ws, a01.y);
            ffma2(acc[1][2], ws, a23.x); ffma2(acc[1][3], ws, a23.y);
            ws = splat2(w0.z);
            ffma2(acc[2][0], ws, a01.x); ffma2(acc[2][1], ws, a01.y);
            ffma2(acc[2][2], ws, a23.x); ffma2(acc[2][3], ws, a23.y);
            ws = splat2(w0.w);
            ffma2(acc[3][0], ws, a01.x); ffma2(acc[3][1], ws, a01.y);
            ffma2(acc[3][2], ws, a23.x); ffma2(acc[3][3], ws, a23.y);
            ws = splat2(w1.x);
            ffma2(acc[4][0], ws, a01.x); ffma2(acc[4][1], ws, a01.y);
            ffma2(acc[4][2], ws, a23.x); ffma2(acc[4][3], ws, a23.y);
            ws = splat2(w1.y);
            ffma2(acc[5][0], ws, a01.x); ffma2(acc[5][1], ws, a01.y);
            ffma2(acc[5][2], ws, a23.x); ffma2(acc[5][3], ws, a23.y);
            ws = splat2(w1.z);
            ffma2(acc[6][0], ws, a01.x); ffma2(acc[6][1], ws, a01.y);
            ffma2(acc[6][2], ws, a23.x); ffma2(acc[6][3], ws, a23.y);
            ws = splat2(w1.w);
            ffma2(acc[7][0], ws, a01.x); ffma2(acc[7][1], ws, a01.y);
            ffma2(acc[7][2], ws, a23.x); ffma2(acc[7][3], ws, a23.y);
        }
        // thread's 8 tokens = window row `warp`, ix 0..7; reverse shift, wrap only
        // between the two 16B halves (xx0 <= 252; xx0+4 may wrap to 0, stays aligned)
        int yy  = (wy * 8 + warp + SSH) & 255;
        int xx0 = wx * 8 + SSH;
        int xx1 = (xx0 + 4) & 255;
        size_t rowbase = (size_t)(b * DIMC + ob) * 65536 + (size_t)yy * 256;
        #pragma unroll
        for (int oo = 0; oo < 8; oo++) {
            size_t rb2 = rowbase + (size_t)oo * 65536;
            *(ulonglong2*)&out[rb2 + xx0] = make_ulonglong2(acc[oo][0], acc[oo][1]);
            *(ulonglong2*)&out[rb2 + xx1] = make_ulonglong2(acc[oo][2], acc[oo][3]);
        }
    }
}

// ---------------- launch ------------------------------------------------------
extern "C" void kernel_launch(void* const* d_in, const int* in_sizes, int n_in,
                              void* d_out, int out_size) {
    const float* x      = (const float*)d_in[0];
    const float* qkv_w  = (const float*)d_in[1];
    const float* qkv_b  = (const float*)d_in[2];
    const float* proj_w = (const float*)d_in[3];
    const float* proj_b = (const float*)d_in[4];
    const float* rpb    = (const float*)d_in[5];
    float* out = (float*)d_out;

    const int smem_bytes = (NTOK * QS + DIMC * NTOK + 1350 + 64) * 4;  // 203288
    cudaFuncSetAttribute(swin_kernel, cudaFuncAttributeMaxDynamicSharedMemorySize,
                         smem_bytes);

    transpose_weights<<<432, 256>>>(qkv_w, proj_w);
    swin_kernel<<<NWIN, 256, smem_bytes>>>(x, qkv_b, proj_b, rpb, out);
}

// round 10
// speedup vs baseline: 1.0024x; 1.0024x over previous
#include <cuda_runtime.h>

#define DIMC 192
#define HEADS 6
#define HD 32
#define SSH 4
#define NTOK 64
#define NWIN 4096
#define SCALE 0.17677669529663687f   // 32^-0.5
#define QS 580                        // qkv_s row stride in floats (64 rows x 580)

typedef unsigned long long u64;

// ---------------- scratch (device globals; no allocations allowed) ----------
__device__ float g_wT[DIMC * 576];    // qkv_w transposed: [k][o]
__device__ float g_pT[DIMC * DIMC];   // proj_w transposed: [k][o]

// ---------------- f32x2 helpers ----------------------------------------------
__device__ __forceinline__ u64 splat2(float v) {
    u64 r; asm("mov.b64 %0,{%1,%1};" : "=l"(r) : "f"(v)); return r;
}
__device__ __forceinline__ void ffma2(u64& d, u64 a, u64 b) {
    asm("fma.rn.f32x2 %0,%1,%2,%0;" : "+l"(d) : "l"(a), "l"(b));
}
__device__ __forceinline__ float2 unpack2(u64 v) {
    float2 r; asm("mov.b64 {%0,%1},%2;" : "=f"(r.x), "=f"(r.y) : "l"(v)); return r;
}

// ---------------- kernel 0: weight transpose ---------------------------------
__global__ void transpose_weights(const float* __restrict__ qkv_w,
                                  const float* __restrict__ proj_w) {
    int idx = blockIdx.x * 256 + threadIdx.x;
    if (idx < 576 * DIMC) {
        int o = idx / DIMC, k = idx % DIMC;
        g_wT[k * 576 + o] = qkv_w[idx];
    }
    if (idx < DIMC * DIMC) {
        int o = idx / DIMC, k = idx % DIMC;
        g_pT[k * DIMC + o] = proj_w[idx];
    }
}

// ---------------- fused per-window megakernel --------------------------------
// smem layout (floats):
//   qkv_s [64][QS]        : QKV activations, token-major  (37120)
//   Xs    [192][64]       : gathered input, channel-major; reused as Os (12288)
//   rpbs  [1350]          : relative position bias table
//   regsh [64] (int)      : shift-mask region id per token
__global__ __launch_bounds__(256, 1) void swin_kernel(
    const float* __restrict__ x, const float* __restrict__ qkv_b,
    const float* __restrict__ proj_b, const float* __restrict__ rpb_table,
    float* __restrict__ out)
{
    extern __shared__ float sm[];
    float* qkv_s = sm;
    float* Xs    = sm + NTOK * QS;
    float* rpbs  = Xs + DIMC * NTOK;
    int*   regsh = (int*)(rpbs + 1350);

    int win = blockIdx.x;
    int b = win >> 10, wy = (win >> 5) & 31, wx = win & 31;
    int tid  = threadIdx.x;
    int lane = tid & 31, warp = tid >> 5;

    // ---- phase 0: gather shifted window + rpb + region ids ----
    int y0 = wy * 8 + SSH, x0 = wx * 8 + SSH;
    for (int idx = tid; idx < DIMC * NTOK; idx += 256) {
        int t = idx & 63, c = idx >> 6;
        int yy = (y0 + (t >> 3)) & 255;
        int xx = (x0 + (t & 7)) & 255;
        Xs[idx] = x[(size_t)(b * DIMC + c) * 65536 + yy * 256 + xx];
    }
    for (int idx = tid; idx < 1350; idx += 256) rpbs[idx] = rpb_table[idx];
    if (tid < 64) {
        int iy = tid >> 3, ix = tid & 7;
        int yt = wy * 8 + iy, xt = wx * 8 + ix;
        int ry = (yt < 248) ? 0 : ((yt < 252) ? 1 : 2);
        int rx = (xt < 248) ? 0 : ((xt < 252) ? 1 : 2);
        regsh[tid] = ry * 3 + rx;
    }
    __syncthreads();

    int t0 = warp * 8;   // 8 tokens per warp (one window row), shared by all lanes

    // ---- phase 1: QKV GEMM  (out[t][o] = sum_k Xs[k][t] * wT[k][o] + b[o]) ----
    {
        const float* __restrict__ wT = g_wT;
        #pragma unroll 1
        for (int pass = 0; pass < 2; pass++) {
            int ob = pass * 256 + lane * 8;
            u64 acc[4][8];                      // [output-pair][token]
            {
                const u64* bp = (const u64*)&qkv_b[ob];
                #pragma unroll
                for (int op = 0; op < 4; op++) {
                    u64 bv = bp[op];
                    #pragma unroll
                    for (int t = 0; t < 8; t++) acc[op][t] = bv;
                }
            }
            #pragma unroll 4
            for (int k = 0; k < DIMC; k++) {
                float4 a01 = *(const float4*)&Xs[k * 64 + t0];      // broadcast LDS
                float4 a23 = *(const float4*)&Xs[k * 64 + t0 + 4];
                const u64* wr = (const u64*)&wT[k * 576 + ob];      // coalesced LDG
                u64 w0 = wr[0], w1 = wr[1], w2 = wr[2], w3 = wr[3];
                u64 as[8];
                as[0] = splat2(a01.x); as[1] = splat2(a01.y);
                as[2] = splat2(a01.z); as[3] = splat2(a01.w);
                as[4] = splat2(a23.x); as[5] = splat2(a23.y);
                as[6] = splat2(a23.z); as[7] = splat2(a23.w);
                #pragma unroll
                for (int t = 0; t < 8; t++) {
                    ffma2(acc[0][t], w0, as[t]);
                    ffma2(acc[1][t], w1, as[t]);
                    ffma2(acc[2][t], w2, as[t]);
                    ffma2(acc[3][t], w3, as[t]);
                }
            }
            #pragma unroll
            for (int t = 0; t < 8; t++) {
                ulonglong2* dst = (ulonglong2*)&qkv_s[(t0 + t) * QS + ob];
                dst[0] = make_ulonglong2(acc[0][t], acc[1][t]);
                dst[1] = make_ulonglong2(acc[2][t], acc[3][t]);
            }
        }
        // tail pass: outputs 512..575 (2 per lane)
        {
            int ob = 512 + lane * 2;
            u64 acc[8];
            u64 bv = *(const u64*)&qkv_b[ob];
            #pragma unroll
            for (int t = 0; t < 8; t++) acc[t] = bv;
            #pragma unroll 4
            for (int k = 0; k < DIMC; k++) {
                float4 a01 = *(const float4*)&Xs[k * 64 + t0];
                float4 a23 = *(const float4*)&Xs[k * 64 + t0 + 4];
                u64 w = *(const u64*)&wT[k * 576 + ob];
                ffma2(acc[0], w, splat2(a01.x));
                ffma2(acc[1], w, splat2(a01.y));
                ffma2(acc[2], w, splat2(a01.z));
                ffma2(acc[3], w, splat2(a01.w));
                ffma2(acc[4], w, splat2(a23.x));
                ffma2(acc[5], w, splat2(a23.y));
                ffma2(acc[6], w, splat2(a23.z));
                ffma2(acc[7], w, splat2(a23.w));
            }
            #pragma unroll
            for (int t = 0; t < 8; t++)
                *(u64*)&qkv_s[(t0 + t) * QS + ob] = acc[t];
        }
    }
    __syncthreads();

    // ---- phase 2: attention (6 heads x 64 query rows = 384 items) ----
    for (int it = tid; it < HEADS * NTOK; it += 256) {
        int h = it >> 6, i = it & 63;
        int iy = i >> 3, ix = i & 7;
        int regi = regsh[i];
        u64 q2[16];
        {
            const ulonglong2* qp = (const ulonglong2*)&qkv_s[i * QS + h * HD];
            #pragma unroll
            for (int m = 0; m < 8; m++) {
                ulonglong2 v = qp[m];
                q2[2 * m] = v.x; q2[2 * m + 1] = v.y;
            }
        }
        u64 acc2[16];
        #pragma unroll
        for (int dp = 0; dp < 16; dp++) acc2[dp] = 0ull;
        float l = 0.f;
        const float* kbase = &qkv_s[DIMC + h * HD];
        const float* vbase = &qkv_s[2 * DIMC + h * HD];
        int rb = (iy + 7) * 15 + (ix + 7);
        #pragma unroll 2
        for (int j = 0; j < NTOK; j++) {
            const ulonglong2* kp = (const ulonglong2*)(kbase + j * QS);
            u64 s2 = 0ull;
            #pragma unroll
            for (int m = 0; m < 8; m++) {
                ulonglong2 kv = kp[m];
                ffma2(s2, q2[2 * m], kv.x);
                ffma2(s2, q2[2 * m + 1], kv.y);
            }
            float2 sp = unpack2(s2);
            float s = sp.x + sp.y;
            float bias = rpbs[(rb - (j >> 3) * 15 - (j & 7)) * HEADS + h];
            float msk  = (regi != regsh[j]) ? -100.f : 0.f;
            float e = __expf(fmaf(s, SCALE, bias + msk));
            l += e;
            u64 es = splat2(e);
            const ulonglong2* vp = (const ulonglong2*)(vbase + j * QS);
            #pragma unroll
            for (int m = 0; m < 8; m++) {
                ulonglong2 vv = vp[m];
                ffma2(acc2[2 * m], es, vv.x);
                ffma2(acc2[2 * m + 1], es, vv.y);
            }
        }
        float invl = 1.f / l;
        float* Ob = Xs + (h * HD) * 64 + i;   // Os[c][t], reuses Xs region
        #pragma unroll
        for (int dp = 0; dp < 16; dp++) {
            float2 v = unpack2(acc2[dp]);
            Ob[(2 * dp) * 64]     = v.x * invl;
            Ob[(2 * dp + 1) * 64] = v.y * invl;
        }
    }
    __syncthreads();

    // ---- phase 3: proj GEMM + reverse-shift scatter (192 outs: lanes 0..23) ----
    if (lane < 24) {
        int ob = lane * 8;
        u64 acc[8][4];                         // [output][token-pair]
        #pragma unroll
        for (int oo = 0; oo < 8; oo++) {
            u64 bv = splat2(proj_b[ob + oo]);
            #pragma unroll
            for (int tp = 0; tp < 4; tp++) acc[oo][tp] = bv;
        }
        const float* __restrict__ pT = g_pT;
        #pragma unroll 4
        for (int k = 0; k < DIMC; k++) {
            const ulonglong2* ar = (const ulonglong2*)&Xs[k * 64 + t0];   // Os broadcast
            ulonglong2 a01 = ar[0], a23 = ar[1];
            const float4* wr = (const float4*)&pT[k * DIMC + ob];
            float4 w0 = wr[0], w1 = wr[1];
            u64 ws;
            ws = splat2(w0.x);
            ffma2(acc[0][0], ws, a01.x); ffma2(acc[0][1], ws, a01.y);
            ffma2(acc[0][2], ws, a23.x); ffma2(acc[0][3], ws, a23.y);
            ws = splat2(w0.y);
            ffma2(acc[1][0], ws, a01.x); ffma2(acc[1][1], ws, a01.y);
            ffma2(acc[1][2], ws, a23.x); ffma2(acc[1][3], ws, a23.y);
            ws = splat2(w0.z);
            ffma2(acc[2][0], ws, a01.x); ffma2(acc[2][1], ws, a01.y);
            ffma2(acc[2][2], ws, a23.x); ffma2(acc[2][3], ws, a23.y);
            ws = splat2(w0.w);
            ffma2(acc[3][0], ws, a01.x); ffma2(acc[3][1], ws, a01.y);
            ffma2(acc[3][2], ws, a23.x); ffma2(acc[3][3], ws, a23.y);
            ws = splat2(w1.x);
            ffma2(acc[4][0], ws, a01.x); ffma2(acc[4][1], ws, a01.y);
            ffma2(acc[4][2], ws, a23.x); ffma2(acc[4][3], ws, a23.y);
            ws = splat2(w1.y);
            ffma2(acc[5][0], ws, a01.x); ffma2(acc[5][1], ws, a01.y);
            ffma2(acc[5][2], ws, a23.x); ffma2(acc[5][3], ws, a23.y);
            ws = splat2(w1.z);
            ffma2(acc[6][0], ws, a01.x); ffma2(acc[6][1], ws, a01.y);
            ffma2(acc[6][2], ws, a23.x); ffma2(acc[6][3], ws, a23.y);
            ws = splat2(w1.w);
            ffma2(acc[7][0], ws, a01.x); ffma2(acc[7][1], ws, a01.y);
            ffma2(acc[7][2], ws, a23.x); ffma2(acc[7][3], ws, a23.y);
        }
        // thread's 8 tokens = window row `warp`, ix 0..7; reverse shift, wrap only
        // between the two 16B halves (xx0 <= 252; xx0+4 may wrap to 0, stays aligned)
        int yy  = (wy * 8 + warp + SSH) & 255;
        int xx0 = wx * 8 + SSH;
        int xx1 = (xx0 + 4) & 255;
        size_t rowbase = (size_t)(b * DIMC + ob) * 65536 + (size_t)yy * 256;
        #pragma unroll
        for (int oo = 0; oo < 8; oo++) {
            size_t rb2 = rowbase + (size_t)oo * 65536;
            *(ulonglong2*)&out[rb2 + xx0] = make_ulonglong2(acc[oo][0], acc[oo][1]);
            *(ulonglong2*)&out[rb2 + xx1] = make_ulonglong2(acc[oo][2], acc[oo][3]);
        }
    }
}

// ---------------- launch ------------------------------------------------------
extern "C" void kernel_launch(void* const* d_in, const int* in_sizes, int n_in,
                              void* d_out, int out_size) {
    const float* x      = (const float*)d_in[0];
    const float* qkv_w  = (const float*)d_in[1];
    const float* qkv_b  = (const float*)d_in[2];
    const float* proj_w = (const float*)d_in[3];
    const float* proj_b = (const float*)d_in[4];
    const float* rpb    = (const float*)d_in[5];
    float* out = (float*)d_out;

    const int smem_bytes = (NTOK * QS + DIMC * NTOK + 1350 + 64) * 4;  // 203288
    cudaFuncSetAttribute(swin_kernel, cudaFuncAttributeMaxDynamicSharedMemorySize,
                         smem_bytes);

    transpose_weights<<<432, 256>>>(qkv_w, proj_w);
    swin_kernel<<<NWIN, 256, smem_bytes>>>(x, qkv_b, proj_b, rpb, out);
}

// round 11
// speedup vs baseline: 1.1242x; 1.1215x over previous
#include <cuda_runtime.h>

#define DIMC 192
#define HEADS 6
#define HD 32
#define SSH 4
#define NTOK 64
#define NWIN 4096
#define SCALE 0.17677669529663687f   // 32^-0.5
#define QROW 576                      // g_qkv row stride (floats)

typedef unsigned long long u64;

// ---------------- scratch (device globals; no allocations allowed) ----------
__device__ float g_qkv[(size_t)NWIN * NTOK * QROW];   // [win][t][o(576)]
__device__ float g_o  [(size_t)NWIN * DIMC * NTOK];   // [win][c][t]
__device__ float g_wT [DIMC * 576];                   // qkv_w transposed: [k][o]
__device__ float g_pT [DIMC * DIMC];                  // proj_w transposed: [k][o]

// ---------------- f32x2 helpers ----------------------------------------------
__device__ __forceinline__ u64 splat2(float v) {
    u64 r; asm("mov.b64 %0,{%1,%1};" : "=l"(r) : "f"(v)); return r;
}
__device__ __forceinline__ void ffma2(u64& d, u64 a, u64 b) {
    asm("fma.rn.f32x2 %0,%1,%2,%0;" : "+l"(d) : "l"(a), "l"(b));
}
__device__ __forceinline__ float2 unpack2(u64 v) {
    float2 r; asm("mov.b64 {%0,%1},%2;" : "=f"(r.x), "=f"(r.y) : "l"(v)); return r;
}

// ---------------- kernel 0: weight transpose ---------------------------------
__global__ void transpose_weights(const float* __restrict__ qkv_w,
                                  const float* __restrict__ proj_w) {
    int idx = blockIdx.x * 256 + threadIdx.x;
    if (idx < 576 * DIMC) {
        int o = idx / DIMC, k = idx % DIMC;
        g_wT[k * 576 + o] = qkv_w[idx];
    }
    if (idx < DIMC * DIMC) {
        int o = idx / DIMC, k = idx % DIMC;
        g_pT[k * DIMC + o] = proj_w[idx];
    }
}

// ---------------- kernel 1: gather + QKV GEMM ---------------------------------
// One CTA per window. Xs[c][t] in smem; out[t][o] = sum_k Xs[k][t]*wT[k][o] + b.
// warp owns tokens t0..t0+7 (one window row); lane owns 8 outputs per pass.
__global__ __launch_bounds__(256, 2) void qkv_kernel(const float* __restrict__ x,
                                                     const float* __restrict__ qkv_b) {
    __shared__ float Xs[DIMC * NTOK];   // 48KB
    int win = blockIdx.x;
    int b = win >> 10, wy = (win >> 5) & 31, wx = win & 31;
    int tid = threadIdx.x;
    int lane = tid & 31, warp = tid >> 5;

    int y0 = wy * 8 + SSH, x0 = wx * 8 + SSH;
    for (int idx = tid; idx < DIMC * NTOK; idx += 256) {
        int t = idx & 63, c = idx >> 6;
        int yy = (y0 + (t >> 3)) & 255;
        int xx = (x0 + (t & 7)) & 255;
        Xs[idx] = x[(size_t)(b * DIMC + c) * 65536 + yy * 256 + xx];
    }
    __syncthreads();

    int t0 = warp * 8;
    float* gq = g_qkv + (size_t)win * (NTOK * QROW);
    const float* __restrict__ wT = g_wT;

    #pragma unroll 1
    for (int pass = 0; pass < 2; pass++) {
        int ob = pass * 256 + lane * 8;
        u64 acc[4][8];                       // [output-pair][token]
        {
            const u64* bp = (const u64*)&qkv_b[ob];
            #pragma unroll
            for (int op = 0; op < 4; op++) {
                u64 bv = bp[op];
                #pragma unroll
                for (int t = 0; t < 8; t++) acc[op][t] = bv;
            }
        }
        #pragma unroll 4
        for (int k = 0; k < DIMC; k++) {
            float4 a01 = *(const float4*)&Xs[k * 64 + t0];      // broadcast LDS
            float4 a23 = *(const float4*)&Xs[k * 64 + t0 + 4];
            const u64* wr = (const u64*)&wT[k * 576 + ob];      // coalesced LDG
            u64 w0 = wr[0], w1 = wr[1], w2 = wr[2], w3 = wr[3];
            u64 as[8];
            as[0] = splat2(a01.x); as[1] = splat2(a01.y);
            as[2] = splat2(a01.z); as[3] = splat2(a01.w);
            as[4] = splat2(a23.x); as[5] = splat2(a23.y);
            as[6] = splat2(a23.z); as[7] = splat2(a23.w);
            #pragma unroll
            for (int t = 0; t < 8; t++) {
                ffma2(acc[0][t], w0, as[t]);
                ffma2(acc[1][t], w1, as[t]);
                ffma2(acc[2][t], w2, as[t]);
                ffma2(acc[3][t], w3, as[t]);
            }
        }
        #pragma unroll
        for (int t = 0; t < 8; t++) {
            ulonglong2* dst = (ulonglong2*)&gq[(size_t)(t0 + t) * QROW + ob];
            dst[0] = make_ulonglong2(acc[0][t], acc[1][t]);
            dst[1] = make_ulonglong2(acc[2][t], acc[3][t]);
        }
    }
    // tail: outputs 512..575 (2 per lane)
    {
        int ob = 512 + lane * 2;
        u64 acc[8];
        u64 bv = *(const u64*)&qkv_b[ob];
        #pragma unroll
        for (int t = 0; t < 8; t++) acc[t] = bv;
        #pragma unroll 4
        for (int k = 0; k < DIMC; k++) {
            float4 a01 = *(const float4*)&Xs[k * 64 + t0];
            float4 a23 = *(const float4*)&Xs[k * 64 + t0 + 4];
            u64 w = *(const u64*)&wT[k * 576 + ob];
            ffma2(acc[0], w, splat2(a01.x));
            ffma2(acc[1], w, splat2(a01.y));
            ffma2(acc[2], w, splat2(a01.z));
            ffma2(acc[3], w, splat2(a01.w));
            ffma2(acc[4], w, splat2(a23.x));
            ffma2(acc[5], w, splat2(a23.y));
            ffma2(acc[6], w, splat2(a23.z));
            ffma2(acc[7], w, splat2(a23.w));
        }
        #pragma unroll
        for (int t = 0; t < 8; t++)
            *(u64*)&gq[(size_t)(t0 + t) * QROW + ob] = acc[t];
    }
}

// ---------------- kernel 2: windowed attention --------------------------------
// grid (4096, 6), 64 threads; thread i = query row i of (window, head).
__global__ __launch_bounds__(64) void attn_kernel(const float* __restrict__ rpb_table) {
    __shared__ float Ks[NTOK][HD];     // token-major rows (128B)
    __shared__ float Vs[NTOK][HD];
    __shared__ float rpbs[225];        // this head's bias slice
    __shared__ int   regsh[NTOK];

    int win = blockIdx.x, h = blockIdx.y;
    int wy = (win >> 5) & 31, wx = win & 31;
    int i = threadIdx.x;

    const float* base = g_qkv + (size_t)win * (NTOK * QROW);
    {
        const float4* krow = (const float4*)(base + (size_t)i * QROW + DIMC + h * HD);
        const float4* vrow = (const float4*)(base + (size_t)i * QROW + 2 * DIMC + h * HD);
        #pragma unroll
        for (int m = 0; m < 8; m++) {
            ((float4*)Ks[i])[m] = krow[m];
            ((float4*)Vs[i])[m] = vrow[m];
        }
    }
    for (int idx = i; idx < 225; idx += 64) rpbs[idx] = rpb_table[idx * HEADS + h];
    {
        int iy = i >> 3, ix = i & 7;
        int yt = wy * 8 + iy, xt = wx * 8 + ix;
        int ry = (yt < 248) ? 0 : ((yt < 252) ? 1 : 2);
        int rx = (xt < 248) ? 0 : ((xt < 252) ? 1 : 2);
        regsh[i] = ry * 3 + rx;
    }

    u64 q2[16];
    {
        const ulonglong2* qp = (const ulonglong2*)(base + (size_t)i * QROW + h * HD);
        #pragma unroll
        for (int m = 0; m < 8; m++) {
            ulonglong2 v = qp[m];
            q2[2 * m] = v.x; q2[2 * m + 1] = v.y;
        }
    }
    __syncthreads();

    int iy = i >> 3, ix = i & 7;
    int regi = regsh[i];
    int rb = (iy + 7) * 15 + (ix + 7);

    float l = 0.f;
    u64 acc2[16];
    #pragma unroll
    for (int dp = 0; dp < 16; dp++) acc2[dp] = 0ull;

    #pragma unroll 2
    for (int j = 0; j < NTOK; j++) {
        const ulonglong2* kp = (const ulonglong2*)Ks[j];
        u64 s2 = 0ull;
        #pragma unroll
        for (int m = 0; m < 8; m++) {
            ulonglong2 kv = kp[m];
            ffma2(s2, q2[2 * m], kv.x);
            ffma2(s2, q2[2 * m + 1], kv.y);
        }
        float2 sp = unpack2(s2);
        float s = sp.x + sp.y;
        float bias = rpbs[rb - (j >> 3) * 15 - (j & 7)];
        float msk  = (regi != regsh[j]) ? -100.f : 0.f;
        float e = __expf(fmaf(s, SCALE, bias + msk));
        l += e;
        u64 es = splat2(e);
        const ulonglong2* vp = (const ulonglong2*)Vs[j];
        #pragma unroll
        for (int m = 0; m < 8; m++) {
            ulonglong2 vv = vp[m];
            ffma2(acc2[2 * m], es, vv.x);
            ffma2(acc2[2 * m + 1], es, vv.y);
        }
    }

    float invl = 1.f / l;
    float* Og = g_o + (size_t)win * (DIMC * NTOK) + (size_t)(h * HD) * 64 + i;
    #pragma unroll
    for (int dp = 0; dp < 16; dp++) {
        float2 v = unpack2(acc2[dp]);
        Og[(2 * dp) * 64]     = v.x * invl;   // coalesced across i per channel
        Og[(2 * dp + 1) * 64] = v.y * invl;
    }
}

// ---------------- kernel 3: proj GEMM + reverse-shift scatter -----------------
// warp = 8 tokens (window row), lane = 6 output channels; token-pair packing? no:
// acc[cp][t]: cp packs channel pairs (ob+2cp, ob+2cp+1) at token t.
__global__ __launch_bounds__(256, 2) void proj_kernel(const float* __restrict__ proj_b,
                                                      float* __restrict__ out) {
    __shared__ float Os[DIMC * NTOK];  // [c][t] 48KB
    int win = blockIdx.x;
    int b = win >> 10, wy = (win >> 5) & 31, wx = win & 31;
    int tid = threadIdx.x;
    int lane = tid & 31, warp = tid >> 5;

    const float* src = g_o + (size_t)win * (DIMC * NTOK);
    for (int idx = tid; idx < DIMC * NTOK / 4; idx += 256)
        ((float4*)Os)[idx] = ((const float4*)src)[idx];
    __syncthreads();

    int t0 = warp * 8;
    int ob = lane * 6;
    u64 acc[3][8];
    {
        const u64* bp = (const u64*)&proj_b[ob];   // 24B offset: 8B aligned
        #pragma unroll
        for (int cp = 0; cp < 3; cp++) {
            u64 bv = bp[cp];
            #pragma unroll
            for (int t = 0; t < 8; t++) acc[cp][t] = bv;
        }
    }
    const float* __restrict__ pT = g_pT;
    #pragma unroll 4
    for (int k = 0; k < DIMC; k++) {
        float4 a01 = *(const float4*)&Os[k * 64 + t0];
        float4 a23 = *(const float4*)&Os[k * 64 + t0 + 4];
        const u64* wr = (const u64*)&pT[k * DIMC + ob];
        u64 w0 = wr[0], w1 = wr[1], w2 = wr[2];
        u64 as[8];
        as[0] = splat2(a01.x); as[1] = splat2(a01.y);
        as[2] = splat2(a01.z); as[3] = splat2(a01.w);
        as[4] = splat2(a23.x); as[5] = splat2(a23.y);
        as[6] = splat2(a23.z); as[7] = splat2(a23.w);
        #pragma unroll
        for (int t = 0; t < 8; t++) {
            ffma2(acc[0][t], w0, as[t]);
            ffma2(acc[1][t], w1, as[t]);
            ffma2(acc[2][t], w2, as[t]);
        }
    }
    // scatter with reverse shift: tokens t0..t0+7 = window row `warp`
    int yy  = (wy * 8 + warp + SSH) & 255;
    int xx0 = wx * 8 + SSH;            // <= 252, 16B aligned
    int xx1 = (xx0 + 4) & 255;         // may wrap to 0, stays aligned
    size_t rowbase = (size_t)(b * DIMC + ob) * 65536 + (size_t)yy * 256;
    #pragma unroll
    for (int cp = 0; cp < 3; cp++) {
        float2 u0 = unpack2(acc[cp][0]), u1 = unpack2(acc[cp][1]);
        float2 u2 = unpack2(acc[cp][2]), u3 = unpack2(acc[cp][3]);
        float2 u4 = unpack2(acc[cp][4]), u5 = unpack2(acc[cp][5]);
        float2 u6 = unpack2(acc[cp][6]), u7 = unpack2(acc[cp][7]);
        size_t r0 = rowbase + (size_t)(2 * cp) * 65536;
        size_t r1 = rowbase + (size_t)(2 * cp + 1) * 65536;
        *(float4*)&out[r0 + xx0] = make_float4(u0.x, u1.x, u2.x, u3.x);
        *(float4*)&out[r0 + xx1] = make_float4(u4.x, u5.x, u6.x, u7.x);
        *(float4*)&out[r1 + xx0] = make_float4(u0.y, u1.y, u2.y, u3.y);
        *(float4*)&out[r1 + xx1] = make_float4(u4.y, u5.y, u6.y, u7.y);
    }
}

// ---------------- launch ------------------------------------------------------
extern "C" void kernel_launch(void* const* d_in, const int* in_sizes, int n_in,
                              void* d_out, int out_size) {
    const float* x      = (const float*)d_in[0];
    const float* qkv_w  = (const float*)d_in[1];
    const float* qkv_b  = (const float*)d_in[2];
    const float* proj_w = (const float*)d_in[3];
    const float* proj_b = (const float*)d_in[4];
    const float* rpb    = (const float*)d_in[5];
    float* out = (float*)d_out;

    transpose_weights<<<432, 256>>>(qkv_w, proj_w);
    qkv_kernel<<<NWIN, 256>>>(x, qkv_b);
    attn_kernel<<<dim3(NWIN, HEADS), 64>>>(rpb);
    proj_kernel<<<NWIN, 256>>>(proj_b, out);
}

// round 12
// speedup vs baseline: 1.1277x; 1.0031x over previous
#include <cuda_runtime.h>

#define DIMC 192
#define HEADS 6
#define HD 32
#define SSH 4
#define NTOK 64
#define NWIN 4096
#define SCALE 0.17677669529663687f   // 32^-0.5
#define QROW 576                      // g_qkv row stride (floats)

typedef unsigned long long u64;

// ---------------- scratch (device globals; no allocations allowed) ----------
__device__ float g_qkv[(size_t)NWIN * NTOK * QROW];   // [win][t][o(576)]
__device__ float g_o  [(size_t)NWIN * DIMC * NTOK];   // [win][c][t]
__device__ float g_wT [DIMC * 576];                   // qkv_w transposed: [k][o]
__device__ float g_pT [DIMC * DIMC];                  // proj_w transposed: [k][o]

// ---------------- f32x2 helpers ----------------------------------------------
__device__ __forceinline__ u64 splat2(float v) {
    u64 r; asm("mov.b64 %0,{%1,%1};" : "=l"(r) : "f"(v)); return r;
}
__device__ __forceinline__ void ffma2(u64& d, u64 a, u64 b) {
    asm("fma.rn.f32x2 %0,%1,%2,%0;" : "+l"(d) : "l"(a), "l"(b));
}
__device__ __forceinline__ float2 unpack2(u64 v) {
    float2 r; asm("mov.b64 {%0,%1},%2;" : "=f"(r.x), "=f"(r.y) : "l"(v)); return r;
}

// ---------------- kernel 0: weight transpose ---------------------------------
__global__ void transpose_weights(const float* __restrict__ qkv_w,
                                  const float* __restrict__ proj_w) {
    int idx = blockIdx.x * 256 + threadIdx.x;
    if (idx < 576 * DIMC) {
        int o = idx / DIMC, k = idx % DIMC;
        g_wT[k * 576 + o] = qkv_w[idx];
    }
    if (idx < DIMC * DIMC) {
        int o = idx / DIMC, k = idx % DIMC;
        g_pT[k * DIMC + o] = proj_w[idx];
    }
}

// ---------------- kernel 1: gather + QKV GEMM ---------------------------------
// One CTA per window. Xs[c][t] in smem; out[t][o] = sum_k Xs[k][t]*wT[k][o] + b.
// warp owns tokens t0..t0+7 (one window row); lane owns 8 outputs per pass.
__global__ __launch_bounds__(256, 2) void qkv_kernel(const float* __restrict__ x,
                                                     const float* __restrict__ qkv_b) {
    __shared__ float Xs[DIMC * NTOK];   // 48KB
    int win = blockIdx.x;
    int b = win >> 10, wy = (win >> 5) & 31, wx = win & 31;
    int tid = threadIdx.x;
    int lane = tid & 31, warp = tid >> 5;

    int y0 = wy * 8 + SSH, x0 = wx * 8 + SSH;
    for (int idx = tid; idx < DIMC * NTOK; idx += 256) {
        int t = idx & 63, c = idx >> 6;
        int yy = (y0 + (t >> 3)) & 255;
        int xx = (x0 + (t & 7)) & 255;
        Xs[idx] = x[(size_t)(b * DIMC + c) * 65536 + yy * 256 + xx];
    }
    __syncthreads();

    int t0 = warp * 8;
    float* gq = g_qkv + (size_t)win * (NTOK * QROW);
    const float* __restrict__ wT = g_wT;

    #pragma unroll 1
    for (int pass = 0; pass < 2; pass++) {
        int ob = pass * 256 + lane * 8;
        u64 acc[4][8];                       // [output-pair][token]
        {
            const u64* bp = (const u64*)&qkv_b[ob];
            #pragma unroll
            for (int op = 0; op < 4; op++) {
                u64 bv = bp[op];
                #pragma unroll
                for (int t = 0; t < 8; t++) acc[op][t] = bv;
            }
        }
        #pragma unroll 4
        for (int k = 0; k < DIMC; k++) {
            float4 a01 = *(const float4*)&Xs[k * 64 + t0];      // broadcast LDS
            float4 a23 = *(const float4*)&Xs[k * 64 + t0 + 4];
            const u64* wr = (const u64*)&wT[k * 576 + ob];      // coalesced LDG
            u64 w0 = wr[0], w1 = wr[1], w2 = wr[2], w3 = wr[3];
            u64 as[8];
            as[0] = splat2(a01.x); as[1] = splat2(a01.y);
            as[2] = splat2(a01.z); as[3] = splat2(a01.w);
            as[4] = splat2(a23.x); as[5] = splat2(a23.y);
            as[6] = splat2(a23.z); as[7] = splat2(a23.w);
            #pragma unroll
            for (int t = 0; t < 8; t++) {
                ffma2(acc[0][t], w0, as[t]);
                ffma2(acc[1][t], w1, as[t]);
                ffma2(acc[2][t], w2, as[t]);
                ffma2(acc[3][t], w3, as[t]);
            }
        }
        #pragma unroll
        for (int t = 0; t < 8; t++) {
            ulonglong2* dst = (ulonglong2*)&gq[(size_t)(t0 + t) * QROW + ob];
            dst[0] = make_ulonglong2(acc[0][t], acc[1][t]);
            dst[1] = make_ulonglong2(acc[2][t], acc[3][t]);
        }
    }
    // tail: outputs 512..575 (2 per lane)
    {
        int ob = 512 + lane * 2;
        u64 acc[8];
        u64 bv = *(const u64*)&qkv_b[ob];
        #pragma unroll
        for (int t = 0; t < 8; t++) acc[t] = bv;
        #pragma unroll 4
        for (int k = 0; k < DIMC; k++) {
            float4 a01 = *(const float4*)&Xs[k * 64 + t0];
            float4 a23 = *(const float4*)&Xs[k * 64 + t0 + 4];
            u64 w = *(const u64*)&wT[k * 576 + ob];
            ffma2(acc[0], w, splat2(a01.x));
            ffma2(acc[1], w, splat2(a01.y));
            ffma2(acc[2], w, splat2(a01.z));
            ffma2(acc[3], w, splat2(a01.w));
            ffma2(acc[4], w, splat2(a23.x));
            ffma2(acc[5], w, splat2(a23.y));
            ffma2(acc[6], w, splat2(a23.z));
            ffma2(acc[7], w, splat2(a23.w));
        }
        #pragma unroll
        for (int t = 0; t < 8; t++)
            *(u64*)&gq[(size_t)(t0 + t) * QROW + ob] = acc[t];
    }
}

// ---------------- kernel 2: windowed attention --------------------------------
// grid (4096, 6), 64 threads; thread i = query row i of (window, head).
__global__ __launch_bounds__(64) void attn_kernel(const float* __restrict__ rpb_table) {
    __shared__ float Ks[NTOK][HD];     // token-major rows (128B)
    __shared__ float Vs[NTOK][HD];
    __shared__ float rpbs[225];        // this head's bias slice
    __shared__ int   regsh[NTOK];

    int win = blockIdx.x, h = blockIdx.y;
    int wy = (win >> 5) & 31, wx = win & 31;
    int i = threadIdx.x;

    const float* base = g_qkv + (size_t)win * (NTOK * QROW);
    {
        const float4* krow = (const float4*)(base + (size_t)i * QROW + DIMC + h * HD);
        const float4* vrow = (const float4*)(base + (size_t)i * QROW + 2 * DIMC + h * HD);
        #pragma unroll
        for (int m = 0; m < 8; m++) {
            ((float4*)Ks[i])[m] = krow[m];
            ((float4*)Vs[i])[m] = vrow[m];
        }
    }
    for (int idx = i; idx < 225; idx += 64) rpbs[idx] = rpb_table[idx * HEADS + h];
    {
        int iy = i >> 3, ix = i & 7;
        int yt = wy * 8 + iy, xt = wx * 8 + ix;
        int ry = (yt < 248) ? 0 : ((yt < 252) ? 1 : 2);
        int rx = (xt < 248) ? 0 : ((xt < 252) ? 1 : 2);
        regsh[i] = ry * 3 + rx;
    }

    u64 q2[16];
    {
        const ulonglong2* qp = (const ulonglong2*)(base + (size_t)i * QROW + h * HD);
        #pragma unroll
        for (int m = 0; m < 8; m++) {
            ulonglong2 v = qp[m];
            q2[2 * m] = v.x; q2[2 * m + 1] = v.y;
        }
    }
    __syncthreads();

    int iy = i >> 3, ix = i & 7;
    int regi = regsh[i];
    int rb = (iy + 7) * 15 + (ix + 7);

    float l = 0.f;
    u64 acc2[16];
    #pragma unroll
    for (int dp = 0; dp < 16; dp++) acc2[dp] = 0ull;

    #pragma unroll 2
    for (int j = 0; j < NTOK; j++) {
        const ulonglong2* kp = (const ulonglong2*)Ks[j];
        u64 s2 = 0ull;
        #pragma unroll
        for (int m = 0; m < 8; m++) {
            ulonglong2 kv = kp[m];
            ffma2(s2, q2[2 * m], kv.x);
            ffma2(s2, q2[2 * m + 1], kv.y);
        }
        float2 sp = unpack2(s2);
        float s = sp.x + sp.y;
        float bias = rpbs[rb - (j >> 3) * 15 - (j & 7)];
        float msk  = (regi != regsh[j]) ? -100.f : 0.f;
        float e = __expf(fmaf(s, SCALE, bias + msk));
        l += e;
        u64 es = splat2(e);
        const ulonglong2* vp = (const ulonglong2*)Vs[j];
        #pragma unroll
        for (int m = 0; m < 8; m++) {
            ulonglong2 vv = vp[m];
            ffma2(acc2[2 * m], es, vv.x);
            ffma2(acc2[2 * m + 1], es, vv.y);
        }
    }

    float invl = 1.f / l;
    float* Og = g_o + (size_t)win * (DIMC * NTOK) + (size_t)(h * HD) * 64 + i;
    #pragma unroll
    for (int dp = 0; dp < 16; dp++) {
        float2 v = unpack2(acc2[dp]);
        Og[(2 * dp) * 64]     = v.x * invl;   // coalesced across i per channel
        Og[(2 * dp + 1) * 64] = v.y * invl;
    }
}

// ---------------- kernel 3: proj GEMM + reverse-shift scatter -----------------
// warp = 8 tokens (window row), lane = 6 output channels; token-pair packing? no:
// acc[cp][t]: cp packs channel pairs (ob+2cp, ob+2cp+1) at token t.
__global__ __launch_bounds__(256, 2) void proj_kernel(const float* __restrict__ proj_b,
                                                      float* __restrict__ out) {
    __shared__ float Os[DIMC * NTOK];  // [c][t] 48KB
    int win = blockIdx.x;
    int b = win >> 10, wy = (win >> 5) & 31, wx = win & 31;
    int tid = threadIdx.x;
    int lane = tid & 31, warp = tid >> 5;

    const float* src = g_o + (size_t)win * (DIMC * NTOK);
    for (int idx = tid; idx < DIMC * NTOK / 4; idx += 256)
        ((float4*)Os)[idx] = ((const float4*)src)[idx];
    __syncthreads();

    int t0 = warp * 8;
    int ob = lane * 6;
    u64 acc[3][8];
    {
        const u64* bp = (const u64*)&proj_b[ob];   // 24B offset: 8B aligned
        #pragma unroll
        for (int cp = 0; cp < 3; cp++) {
            u64 bv = bp[cp];
            #pragma unroll
            for (int t = 0; t < 8; t++) acc[cp][t] = bv;
        }
    }
    const float* __restrict__ pT = g_pT;
    #pragma unroll 4
    for (int k = 0; k < DIMC; k++) {
        float4 a01 = *(const float4*)&Os[k * 64 + t0];
        float4 a23 = *(const float4*)&Os[k * 64 + t0 + 4];
        const u64* wr = (const u64*)&pT[k * DIMC + ob];
        u64 w0 = wr[0], w1 = wr[1], w2 = wr[2];
        u64 as[8];
        as[0] = splat2(a01.x); as[1] = splat2(a01.y);
        as[2] = splat2(a01.z); as[3] = splat2(a01.w);
        as[4] = splat2(a23.x); as[5] = splat2(a23.y);
        as[6] = splat2(a23.z); as[7] = splat2(a23.w);
        #pragma unroll
        for (int t = 0; t < 8; t++) {
            ffma2(acc[0][t], w0, as[t]);
            ffma2(acc[1][t], w1, as[t]);
            ffma2(acc[2][t], w2, as[t]);
        }
    }
    // scatter with reverse shift: tokens t0..t0+7 = window row `warp`
    int yy  = (wy * 8 + warp + SSH) & 255;
    int xx0 = wx * 8 + SSH;            // <= 252, 16B aligned
    int xx1 = (xx0 + 4) & 255;         // may wrap to 0, stays aligned
    size_t rowbase = (size_t)(b * DIMC + ob) * 65536 + (size_t)yy * 256;
    #pragma unroll
    for (int cp = 0; cp < 3; cp++) {
        float2 u0 = unpack2(acc[cp][0]), u1 = unpack2(acc[cp][1]);
        float2 u2 = unpack2(acc[cp][2]), u3 = unpack2(acc[cp][3]);
        float2 u4 = unpack2(acc[cp][4]), u5 = unpack2(acc[cp][5]);
        float2 u6 = unpack2(acc[cp][6]), u7 = unpack2(acc[cp][7]);
        size_t r0 = rowbase + (size_t)(2 * cp) * 65536;
        size_t r1 = rowbase + (size_t)(2 * cp + 1) * 65536;
        *(float4*)&out[r0 + xx0] = make_float4(u0.x, u1.x, u2.x, u3.x);
        *(float4*)&out[r0 + xx1] = make_float4(u4.x, u5.x, u6.x, u7.x);
        *(float4*)&out[r1 + xx0] = make_float4(u0.y, u1.y, u2.y, u3.y);
        *(float4*)&out[r1 + xx1] = make_float4(u4.y, u5.y, u6.y, u7.y);
    }
}

// ---------------- launch ------------------------------------------------------
extern "C" void kernel_launch(void* const* d_in, const int* in_sizes, int n_in,
                              void* d_out, int out_size) {
    const float* x      = (const float*)d_in[0];
    const float* qkv_w  = (const float*)d_in[1];
    const float* qkv_b  = (const float*)d_in[2];
    const float* proj_w = (const float*)d_in[3];
    const float* proj_b = (const float*)d_in[4];
    const float* rpb    = (const float*)d_in[5];
    float* out = (float*)d_out;

    transpose_weights<<<432, 256>>>(qkv_w, proj_w);
    qkv_kernel<<<NWIN, 256>>>(x, qkv_b);
    attn_kernel<<<dim3(NWIN, HEADS), 64>>>(rpb);
    proj_kernel<<<NWIN, 256>>>(proj_b, out);
}